// round 9
// baseline (speedup 1.0000x reference)
#include <cuda_runtime.h>
#include <cuda_fp16.h>
#include <cstdint>

// LIIF render via fp16 HMMA (mma.sync m16n8k16) on sm_103.
// R9 = R8 (best: 1427us) with k-tile 128 -> 6 pipeline stages.
// M=128 per CTA (32 queries x 4 corners), 256 threads / 8 warps,
// warp tile 128m x 32n; warp-private B strips, cp.async double buffer,
// ldmatrix.x4 A-fragments, no per-stage __syncthreads.
// Layer-0 folded into precomputed projection P'.

namespace {

constexpr int NTHR    = 256;
constexpr int QT      = 32;
constexpr int XS_H    = 264;               // X row stride in halves (132 words)
constexpr int BW_H    = 136;               // B strip row stride in halves (68 words)
constexpr int BW_BUF  = 32 * BW_H;         // halves per strip buffer (4352)
constexpr int NSTAGES = 6;                 // 3 layers x 2 k-tiles of 128

__device__ __half g_wh[196608];            // w1..w3 transposed [l][n][k], fp16
__device__ float  g_proj[4 * 4096 * 256];  // P' = feat@w0f + b0 + cell-terms

__device__ __forceinline__ void cp16(uint32_t dst, const void* src) {
    asm volatile("cp.async.cg.shared.global [%0], [%1], 16;"
                 :: "r"(dst), "l"(src) : "memory");
}
__device__ __forceinline__ void cp_commit() {
    asm volatile("cp.async.commit_group;" ::: "memory");
}
template <int N>
__device__ __forceinline__ void cp_wait() {
    asm volatile("cp.async.wait_group %0;" :: "n"(N) : "memory");
}
__device__ __forceinline__ uint32_t smem_u32(const void* p) {
    uint32_t a;
    asm("{ .reg .u64 t; cvta.to.shared.u64 t, %1; cvt.u32.u64 %0, t; }"
        : "=r"(a) : "l"(p));
    return a;
}
__device__ __forceinline__ void ldsm4(uint32_t& r0, uint32_t& r1,
                                      uint32_t& r2, uint32_t& r3, uint32_t addr) {
    asm volatile("ldmatrix.sync.aligned.m8n8.x4.shared.b16 {%0,%1,%2,%3}, [%4];"
                 : "=r"(r0), "=r"(r1), "=r"(r2), "=r"(r3) : "r"(addr));
}
__device__ __forceinline__ void mma_f16(float c[4], uint32_t a0, uint32_t a1,
                                        uint32_t a2, uint32_t a3,
                                        uint32_t b0, uint32_t b1) {
    asm volatile(
        "mma.sync.aligned.m16n8k16.row.col.f32.f16.f16.f32 "
        "{%0,%1,%2,%3}, {%4,%5,%6,%7}, {%8,%9}, {%0,%1,%2,%3};"
        : "+f"(c[0]), "+f"(c[1]), "+f"(c[2]), "+f"(c[3])
        : "r"(a0), "r"(a1), "r"(a2), "r"(a3), "r"(b0), "r"(b1));
}

// ---------- prep 1: w1..w3 -> fp16, transposed to [l][n][k] ----------
__global__ void prep_w_kernel(const float* __restrict__ w1, const float* __restrict__ w2,
                              const float* __restrict__ w3) {
    const int idx = blockIdx.x * blockDim.x + threadIdx.x;
    if (idx >= 196608) return;
    const int l = idx >> 16;
    const int rem = idx & 65535;
    const int nn = rem >> 8, k = rem & 255;
    const float* w = (l == 0) ? w1 : (l == 1) ? w2 : w3;
    g_wh[idx] = __float2half_rn(w[k * 256 + nn]);
}

// ---------- prep 2: P'[n][idx][c] (fp32, validated R4/R5) ----------
__global__ void prep_proj_kernel(const float* __restrict__ feat,
                                 const float* __restrict__ w0,
                                 const float* __restrict__ b0) {
    __shared__ float sf[64];
    const int blk = blockIdx.x;
    const int n   = blk >> 12;
    const int idx = blk & 4095;
    const int c   = threadIdx.x;
    if (c < 64) sf[c] = feat[((size_t)n * 64 + c) * 4096 + idx];
    __syncthreads();
    float acc = b0[c] + 0.5f * (w0[66 * 256 + c] + w0[67 * 256 + c]);
#pragma unroll 8
    for (int ch = 0; ch < 64; ch++)
        acc = fmaf(sf[ch], w0[ch * 256 + c], acc);
    g_proj[(size_t)blk * 256 + c] = acc;
}

// ---------- main kernel ----------
__global__ __launch_bounds__(NTHR, 1)
void liif_hmma_kernel(const float* __restrict__ w0, const float* __restrict__ w4,
                      const float* __restrict__ b1, const float* __restrict__ b2,
                      const float* __restrict__ b3, const float* __restrict__ b4,
                      float* __restrict__ out)
{
    extern __shared__ __half smem_h[];
    __half* Xs = smem_h;                         // 128 x 264 halves
    __half* Bs = smem_h + 128 * XS_H;            // 8 warps x 2 bufs x 4352 halves
    const uint32_t xs_u = smem_u32(Xs);
    const uint32_t bs_u = smem_u32(Bs);

    __shared__ float s_bias[3][256];
    __shared__ float s_w0r[2][256];
    __shared__ float s_w4[772];
    __shared__ float s_b4[3];
    __shared__ int   s_idx[4][QT];
    __shared__ float s_rel[4][2][QT];
    __shared__ float s_wt[4][QT];
    __shared__ float s_red[128][2][3];

    const int tid  = threadIdx.x;
    const int wid  = tid >> 5;
    const int lane = tid & 31;
    const int g_   = lane >> 2, tig = lane & 3;
    const int n    = blockIdx.y;
    const int q0   = blockIdx.x * QT;

    // per-warp B strip copy: stage st (layer st>>1, k-tile st&1) -> buffer buf
    auto prefetch = [&](int buf, int st) {
        const int l2 = st >> 1, t2 = st & 1;
        const uint32_t dst0 = bs_u + (uint32_t)(wid * 2 * BW_BUF + buf * BW_BUF) * 2u;
#pragma unroll
        for (int j = 0; j < 16; j++) {
            const int e = lane + 32 * j;                 // 0..511
            const int row = e >> 4, ch = e & 15;         // n-row 0..31, 16B chunk 0..15
            const __half* src = g_wh + (((l2 * 256 + wid * 32 + row) << 8) + t2 * 128 + ch * 8);
            cp16(dst0 + (uint32_t)(row * BW_H + ch * 8) * 2u, src);
        }
        cp_commit();
    };

    prefetch(0, 0);     // stage 0 in flight during setup

    for (int i = tid; i < 256; i += NTHR) {
        s_bias[0][i] = b1[i]; s_bias[1][i] = b2[i]; s_bias[2][i] = b3[i];
        s_w0r[0][i] = w0[64 * 256 + i]; s_w0r[1][i] = w0[65 * 256 + i];
    }
    for (int i = tid; i < 768; i += NTHR) s_w4[i] = w4[i];
    if (tid < 3) s_b4[tid] = b4[tid];

    // per-query geometry (validated R1/R3)
    if (tid < QT) {
        const int q = q0 + tid;
        const int yq = q >> 8, xq = q & 255;
        const float c0 = (2.f * (float)yq + 1.f) * (1.f / 256.f) - 1.f;
        const float c1 = (2.f * (float)xq + 1.f) * (1.f / 256.f) - 1.f;
        const float lo = (float)(-1.0 + 1e-6), hi = (float)(1.0 - 1e-6);
        float areas[4];
#pragma unroll
        for (int t = 0; t < 4; t++) {
            const double vx = (t < 2) ? -1.0 : 1.0;
            const double vy = (t & 1) ? 1.0 : -1.0;
            const float shx = (float)(vx * (1.0 / 64.0) + 1e-6);
            const float shy = (float)(vy * (1.0 / 64.0) + 1e-6);
            const float cc0 = fminf(fmaxf(c0 + shx, lo), hi);
            const float cc1 = fminf(fmaxf(c1 + shy, lo), hi);
            int iy = (int)rintf(((cc0 + 1.f) * 64.f - 1.f) * 0.5f);
            int ix = (int)rintf(((cc1 + 1.f) * 64.f - 1.f) * 0.5f);
            iy = min(max(iy, 0), 63); ix = min(max(ix, 0), 63);
            const float qc0 = (2.f * (float)iy + 1.f) * (1.f / 64.f) - 1.f;
            const float qc1 = (2.f * (float)ix + 1.f) * (1.f / 64.f) - 1.f;
            const float r0 = (c0 - qc0) * 64.f;
            const float r1 = (c1 - qc1) * 64.f;
            s_idx[t][tid] = iy * 64 + ix;
            s_rel[t][0][tid] = r0; s_rel[t][1][tid] = r1;
            areas[t] = fabsf(r0 * r1) + 1e-9f;
        }
        const float tot = areas[0] + areas[1] + areas[2] + areas[3];
#pragma unroll
        for (int t = 0; t < 4; t++) s_wt[t][tid] = areas[3 - t] / tot;
    }
    __syncthreads();

    // h0 build: thread = (row, 128-col half); fp32 math, round to fp16
    {
        const int row = tid >> 1, hseg = tid & 1;
        const int t = row >> 5, i = row & 31;
        const int idx = s_idx[t][i];
        const float r0 = s_rel[t][0][i], r1 = s_rel[t][1][i];
        const float4* pp = (const float4*)(g_proj + (((size_t)n << 12) + idx) * 256)
                           + hseg * 32;
        __half2* xw = (__half2*)Xs + row * 132 + hseg * 64;
#pragma unroll
        for (int j = 0; j < 32; j++) {
            const float4 p = pp[j];
            const int c = hseg * 128 + j * 4;
            const float v0 = fmaf(r0, s_w0r[0][c],     fmaf(r1, s_w0r[1][c],     p.x));
            const float v1 = fmaf(r0, s_w0r[0][c + 1], fmaf(r1, s_w0r[1][c + 1], p.y));
            const float v2 = fmaf(r0, s_w0r[0][c + 2], fmaf(r1, s_w0r[1][c + 2], p.z));
            const float v3 = fmaf(r0, s_w0r[0][c + 3], fmaf(r1, s_w0r[1][c + 3], p.w));
            xw[j * 2]     = __floats2half2_rn(fmaxf(v0, 0.f), fmaxf(v1, 0.f));
            xw[j * 2 + 1] = __floats2half2_rn(fmaxf(v2, 0.f), fmaxf(v3, 0.f));
        }
    }
    __syncthreads();

    // ldmatrix per-lane A base: row = lane&15, k-halves add = (lane>>4)*8
    const int lrow = lane & 15;
    const int kadd = (lane >> 4) << 3;
    const uint32_t a_lane = xs_u + (uint32_t)(lrow * XS_H + kadd) * 2u;

    const uint32_t* Bw = (const uint32_t*)(Bs + wid * 2 * BW_BUF);

    float acc[8][4][4];
#pragma unroll
    for (int mt = 0; mt < 8; mt++)
#pragma unroll
        for (int nt = 0; nt < 4; nt++)
#pragma unroll
            for (int r = 0; r < 4; r++) acc[mt][nt][r] = 0.f;

    int buf = 0;
#pragma unroll 1
    for (int st = 0; st < NSTAGES; st++) {
        const int tile = st & 1;

        if (st + 1 < NSTAGES) { prefetch(buf ^ 1, st + 1); cp_wait<1>(); }
        else                  { cp_wait<0>(); }
        // no __syncthreads: B strips are warp-private, Xs is read-only here

        const uint32_t* Bb = Bw + buf * (BW_BUF / 2);
        const uint32_t a_st = a_lane + (uint32_t)(tile * 128) * 2u;  // halves -> bytes

#pragma unroll
        for (int s = 0; s < 8; s++) {            // eight k16 steps per 128-k tile
            uint32_t b0[4], b1[4];
#pragma unroll
            for (int nt = 0; nt < 4; nt++) {
                const int bw = (nt * 8 + g_) * 68 + s * 8 + tig;
                b0[nt] = Bb[bw];
                b1[nt] = Bb[bw + 4];
            }
            const uint32_t a_s = a_st + (uint32_t)(s * 32);
#pragma unroll
            for (int mt = 0; mt < 8; mt++) {
                uint32_t a0, a1, a2, a3;
                ldsm4(a0, a1, a2, a3, a_s + (uint32_t)(mt * 16 * XS_H * 2));
#pragma unroll
                for (int nt = 0; nt < 4; nt++)
                    mma_f16(acc[mt][nt], a0, a1, a2, a3, b0[nt], b1[nt]);
            }
        }
        buf ^= 1;

        if (tile == 1) {                         // layer boundary
            const int le = st >> 1;
            __syncthreads();                     // all reads of Xs done
#pragma unroll
            for (int mt = 0; mt < 8; mt++) {
#pragma unroll
                for (int nt = 0; nt < 4; nt++) {
                    const int c = wid * 32 + nt * 8 + 2 * tig;
                    const float bv0 = s_bias[le][c], bv1 = s_bias[le][c + 1];
                    const float v00 = fmaxf(acc[mt][nt][0] + bv0, 0.f);
                    const float v01 = fmaxf(acc[mt][nt][1] + bv1, 0.f);
                    const float v10 = fmaxf(acc[mt][nt][2] + bv0, 0.f);
                    const float v11 = fmaxf(acc[mt][nt][3] + bv1, 0.f);
                    const int r0 = mt * 16 + g_;
                    __half2* xw = (__half2*)Xs;
                    xw[r0 * 132 + wid * 16 + nt * 4 + tig]       = __floats2half2_rn(v00, v01);
                    xw[(r0 + 8) * 132 + wid * 16 + nt * 4 + tig] = __floats2half2_rn(v10, v11);
                    acc[mt][nt][0] = 0.f; acc[mt][nt][1] = 0.f;
                    acc[mt][nt][2] = 0.f; acc[mt][nt][3] = 0.f;
                }
            }
            __syncthreads();                     // writes visible before next layer
        }
    }

    // final 256->3 layer, fp32: thread = (row, k-half)
    {
        const int row = tid >> 1, hseg = tid & 1;
        const __half2* xw = (const __half2*)Xs + row * 132 + hseg * 64;
        float a0 = 0.f, a1 = 0.f, a2 = 0.f;
#pragma unroll 16
        for (int j = 0; j < 64; j++) {
            const float2 y = __half22float2(xw[j]);
            const float* wr = &s_w4[(hseg * 128 + 2 * j) * 3];
            a0 = fmaf(y.x, wr[0], fmaf(y.y, wr[3], a0));
            a1 = fmaf(y.x, wr[1], fmaf(y.y, wr[4], a1));
            a2 = fmaf(y.x, wr[2], fmaf(y.y, wr[5], a2));
        }
        s_red[row][hseg][0] = a0; s_red[row][hseg][1] = a1; s_red[row][hseg][2] = a2;
    }
    __syncthreads();

    // area-weighted combine + NCHW write
    if (tid < 96) {
        const int i = tid / 3;
        const int o = tid - 3 * (tid / 3);
        float v = 0.f;
#pragma unroll
        for (int t = 0; t < 4; t++) {
            const int row = t * 32 + i;
            const float p = s_b4[o] + s_red[row][0][o] + s_red[row][1][o];
            v += s_wt[t][i] * p;
        }
        out[((size_t)n * 3 + o) * 65536 + q0 + i] = v;
    }
}

} // anonymous namespace

extern "C" void kernel_launch(void* const* d_in, const int* in_sizes, int n_in,
                              void* d_out, int out_size)
{
    (void)in_sizes; (void)n_in; (void)out_size;
    const float* feat = (const float*)d_in[0];
    const float* w0 = (const float*)d_in[1];
    const float* b0 = (const float*)d_in[2];
    const float* w1 = (const float*)d_in[3];
    const float* b1 = (const float*)d_in[4];
    const float* w2 = (const float*)d_in[5];
    const float* b2 = (const float*)d_in[6];
    const float* w3 = (const float*)d_in[7];
    const float* b3 = (const float*)d_in[8];
    const float* w4 = (const float*)d_in[9];
    const float* b4 = (const float*)d_in[10];

    prep_w_kernel<<<(196608 + 255) / 256, 256>>>(w1, w2, w3);
    prep_proj_kernel<<<16384, 256>>>(feat, w0, b0);

    const size_t shmem = (size_t)(128 * XS_H + 8 * 2 * BW_BUF) * sizeof(__half); // 206848 B
    cudaFuncSetAttribute(liif_hmma_kernel,
                         cudaFuncAttributeMaxDynamicSharedMemorySize, (int)shmem);
    dim3 grid(65536 / QT, 4);
    liif_hmma_kernel<<<grid, NTHR, shmem>>>(w0, w4, b1, b2, b3, b4, (float*)d_out);
}

// round 10
// speedup vs baseline: 1.0361x; 1.0361x over previous
#include <cuda_runtime.h>
#include <cuda_fp16.h>
#include <cstdint>

// LIIF render via fp16 HMMA (mma.sync m16n8k16) on sm_103.
// R10 = R8 (best: 1427us) + 3-deep cp.async pipeline (prefetch distance 2).
// M=128 per CTA (32 queries x 4 corners), 256 threads / 8 warps,
// warp tile 128m x 32n, k-tile 64 (12 stages); warp-private B strips,
// ldmatrix.x4 A-fragments, no per-stage __syncthreads.
// Layer-0 folded into precomputed projection P'.

namespace {

constexpr int NTHR    = 256;
constexpr int QT      = 32;
constexpr int XS_H    = 264;               // X row stride in halves (132 words)
constexpr int BW_H    = 72;                // B strip row stride in halves (36 words)
constexpr int BW_BUF  = 32 * BW_H;         // halves per strip buffer (2304)
constexpr int NBUF    = 3;                 // pipeline depth
constexpr int NSTAGES = 12;                // 3 layers x 4 k-tiles of 64

__device__ __half g_wh[196608];            // w1..w3 transposed [l][n][k], fp16
__device__ float  g_proj[4 * 4096 * 256];  // P' = feat@w0f + b0 + cell-terms

__device__ __forceinline__ void cp16(uint32_t dst, const void* src) {
    asm volatile("cp.async.cg.shared.global [%0], [%1], 16;"
                 :: "r"(dst), "l"(src) : "memory");
}
__device__ __forceinline__ void cp_commit() {
    asm volatile("cp.async.commit_group;" ::: "memory");
}
template <int N>
__device__ __forceinline__ void cp_wait() {
    asm volatile("cp.async.wait_group %0;" :: "n"(N) : "memory");
}
__device__ __forceinline__ uint32_t smem_u32(const void* p) {
    uint32_t a;
    asm("{ .reg .u64 t; cvta.to.shared.u64 t, %1; cvt.u32.u64 %0, t; }"
        : "=r"(a) : "l"(p));
    return a;
}
__device__ __forceinline__ void ldsm4(uint32_t& r0, uint32_t& r1,
                                      uint32_t& r2, uint32_t& r3, uint32_t addr) {
    asm volatile("ldmatrix.sync.aligned.m8n8.x4.shared.b16 {%0,%1,%2,%3}, [%4];"
                 : "=r"(r0), "=r"(r1), "=r"(r2), "=r"(r3) : "r"(addr));
}
__device__ __forceinline__ void mma_f16(float c[4], uint32_t a0, uint32_t a1,
                                        uint32_t a2, uint32_t a3,
                                        uint32_t b0, uint32_t b1) {
    asm volatile(
        "mma.sync.aligned.m16n8k16.row.col.f32.f16.f16.f32 "
        "{%0,%1,%2,%3}, {%4,%5,%6,%7}, {%8,%9}, {%0,%1,%2,%3};"
        : "+f"(c[0]), "+f"(c[1]), "+f"(c[2]), "+f"(c[3])
        : "r"(a0), "r"(a1), "r"(a2), "r"(a3), "r"(b0), "r"(b1));
}

// ---------- prep 1: w1..w3 -> fp16, transposed to [l][n][k] ----------
__global__ void prep_w_kernel(const float* __restrict__ w1, const float* __restrict__ w2,
                              const float* __restrict__ w3) {
    const int idx = blockIdx.x * blockDim.x + threadIdx.x;
    if (idx >= 196608) return;
    const int l = idx >> 16;
    const int rem = idx & 65535;
    const int nn = rem >> 8, k = rem & 255;
    const float* w = (l == 0) ? w1 : (l == 1) ? w2 : w3;
    g_wh[idx] = __float2half_rn(w[k * 256 + nn]);
}

// ---------- prep 2: P'[n][idx][c] (fp32, validated R4/R5) ----------
__global__ void prep_proj_kernel(const float* __restrict__ feat,
                                 const float* __restrict__ w0,
                                 const float* __restrict__ b0) {
    __shared__ float sf[64];
    const int blk = blockIdx.x;
    const int n   = blk >> 12;
    const int idx = blk & 4095;
    const int c   = threadIdx.x;
    if (c < 64) sf[c] = feat[((size_t)n * 64 + c) * 4096 + idx];
    __syncthreads();
    float acc = b0[c] + 0.5f * (w0[66 * 256 + c] + w0[67 * 256 + c]);
#pragma unroll 8
    for (int ch = 0; ch < 64; ch++)
        acc = fmaf(sf[ch], w0[ch * 256 + c], acc);
    g_proj[(size_t)blk * 256 + c] = acc;
}

// ---------- main kernel ----------
__global__ __launch_bounds__(NTHR, 1)
void liif_hmma_kernel(const float* __restrict__ w0, const float* __restrict__ w4,
                      const float* __restrict__ b1, const float* __restrict__ b2,
                      const float* __restrict__ b3, const float* __restrict__ b4,
                      float* __restrict__ out)
{
    extern __shared__ __half smem_h[];
    __half* Xs = smem_h;                         // 128 x 264 halves
    __half* Bs = smem_h + 128 * XS_H;            // 8 warps x 3 bufs x 2304 halves
    const uint32_t xs_u = smem_u32(Xs);
    const uint32_t bs_u = smem_u32(Bs);

    __shared__ float s_bias[3][256];
    __shared__ float s_w0r[2][256];
    __shared__ float s_w4[772];
    __shared__ float s_b4[3];
    __shared__ int   s_idx[4][QT];
    __shared__ float s_rel[4][2][QT];
    __shared__ float s_wt[4][QT];
    __shared__ float s_red[128][2][3];

    const int tid  = threadIdx.x;
    const int wid  = tid >> 5;
    const int lane = tid & 31;
    const int g_   = lane >> 2, tig = lane & 3;
    const int n    = blockIdx.y;
    const int q0   = blockIdx.x * QT;

    // per-warp B strip copy: stage st (layer st>>2, tile st&3) -> buffer buf
    auto prefetch = [&](int buf, int st) {
        const int l2 = st >> 2, t2 = st & 3;
        const uint32_t dst0 = bs_u + (uint32_t)((wid * NBUF + buf) * BW_BUF) * 2u;
#pragma unroll
        for (int j = 0; j < 8; j++) {
            const int e = lane + 32 * j;
            const int row = e >> 3, ch = e & 7;          // n-row 0..31, 16B chunk 0..7
            const __half* src = g_wh + (((l2 * 256 + wid * 32 + row) << 8) + t2 * 64 + ch * 8);
            cp16(dst0 + (uint32_t)(row * BW_H + ch * 8) * 2u, src);
        }
        cp_commit();
    };

    prefetch(0, 0);     // stages 0,1 in flight during setup
    prefetch(1, 1);

    for (int i = tid; i < 256; i += NTHR) {
        s_bias[0][i] = b1[i]; s_bias[1][i] = b2[i]; s_bias[2][i] = b3[i];
        s_w0r[0][i] = w0[64 * 256 + i]; s_w0r[1][i] = w0[65 * 256 + i];
    }
    for (int i = tid; i < 768; i += NTHR) s_w4[i] = w4[i];
    if (tid < 3) s_b4[tid] = b4[tid];

    // per-query geometry (validated R1/R3)
    if (tid < QT) {
        const int q = q0 + tid;
        const int yq = q >> 8, xq = q & 255;
        const float c0 = (2.f * (float)yq + 1.f) * (1.f / 256.f) - 1.f;
        const float c1 = (2.f * (float)xq + 1.f) * (1.f / 256.f) - 1.f;
        const float lo = (float)(-1.0 + 1e-6), hi = (float)(1.0 - 1e-6);
        float areas[4];
#pragma unroll
        for (int t = 0; t < 4; t++) {
            const double vx = (t < 2) ? -1.0 : 1.0;
            const double vy = (t & 1) ? 1.0 : -1.0;
            const float shx = (float)(vx * (1.0 / 64.0) + 1e-6);
            const float shy = (float)(vy * (1.0 / 64.0) + 1e-6);
            const float cc0 = fminf(fmaxf(c0 + shx, lo), hi);
            const float cc1 = fminf(fmaxf(c1 + shy, lo), hi);
            int iy = (int)rintf(((cc0 + 1.f) * 64.f - 1.f) * 0.5f);
            int ix = (int)rintf(((cc1 + 1.f) * 64.f - 1.f) * 0.5f);
            iy = min(max(iy, 0), 63); ix = min(max(ix, 0), 63);
            const float qc0 = (2.f * (float)iy + 1.f) * (1.f / 64.f) - 1.f;
            const float qc1 = (2.f * (float)ix + 1.f) * (1.f / 64.f) - 1.f;
            const float r0 = (c0 - qc0) * 64.f;
            const float r1 = (c1 - qc1) * 64.f;
            s_idx[t][tid] = iy * 64 + ix;
            s_rel[t][0][tid] = r0; s_rel[t][1][tid] = r1;
            areas[t] = fabsf(r0 * r1) + 1e-9f;
        }
        const float tot = areas[0] + areas[1] + areas[2] + areas[3];
#pragma unroll
        for (int t = 0; t < 4; t++) s_wt[t][tid] = areas[3 - t] / tot;
    }
    __syncthreads();

    // h0 build: thread = (row, 128-col half); fp32 math, round to fp16
    {
        const int row = tid >> 1, hseg = tid & 1;
        const int t = row >> 5, i = row & 31;
        const int idx = s_idx[t][i];
        const float r0 = s_rel[t][0][i], r1 = s_rel[t][1][i];
        const float4* pp = (const float4*)(g_proj + (((size_t)n << 12) + idx) * 256)
                           + hseg * 32;
        __half2* xw = (__half2*)Xs + row * 132 + hseg * 64;
#pragma unroll
        for (int j = 0; j < 32; j++) {
            const float4 p = pp[j];
            const int c = hseg * 128 + j * 4;
            const float v0 = fmaf(r0, s_w0r[0][c],     fmaf(r1, s_w0r[1][c],     p.x));
            const float v1 = fmaf(r0, s_w0r[0][c + 1], fmaf(r1, s_w0r[1][c + 1], p.y));
            const float v2 = fmaf(r0, s_w0r[0][c + 2], fmaf(r1, s_w0r[1][c + 2], p.z));
            const float v3 = fmaf(r0, s_w0r[0][c + 3], fmaf(r1, s_w0r[1][c + 3], p.w));
            xw[j * 2]     = __floats2half2_rn(fmaxf(v0, 0.f), fmaxf(v1, 0.f));
            xw[j * 2 + 1] = __floats2half2_rn(fmaxf(v2, 0.f), fmaxf(v3, 0.f));
        }
    }
    __syncthreads();

    // ldmatrix per-lane A base: row = lane&15, k-halves add = (lane>>4)*8
    const int lrow = lane & 15;
    const int kadd = (lane >> 4) << 3;
    const uint32_t a_lane = xs_u + (uint32_t)(lrow * XS_H + kadd) * 2u;

    const uint32_t* Bw = (const uint32_t*)(Bs + wid * NBUF * BW_BUF);

    float acc[8][4][4];
#pragma unroll
    for (int mt = 0; mt < 8; mt++)
#pragma unroll
        for (int nt = 0; nt < 4; nt++)
#pragma unroll
            for (int r = 0; r < 4; r++) acc[mt][nt][r] = 0.f;

    int buf = 0;        // buffer holding current stage (st % 3)
#pragma unroll 1
    for (int st = 0; st < NSTAGES; st++) {
        const int tile = st & 3;

        // prefetch distance 2: stage st's copy was issued 2 stages ago
        if (st + 2 < NSTAGES) {
            const int nb = (buf + 2 >= NBUF) ? buf + 2 - NBUF : buf + 2;
            prefetch(nb, st + 2);
            cp_wait<2>();
        } else if (st + 1 < NSTAGES) {
            cp_wait<1>();
        } else {
            cp_wait<0>();
        }
        // no __syncthreads: B strips are warp-private, Xs is read-only here

        const uint32_t* Bb = Bw + buf * (BW_BUF / 2);
        const uint32_t a_st = a_lane + (uint32_t)(tile * 64) * 2u;   // halves -> bytes

#pragma unroll
        for (int s = 0; s < 4; s++) {            // four k16 steps per 64-k tile
            uint32_t b0[4], b1[4];
#pragma unroll
            for (int nt = 0; nt < 4; nt++) {
                const int bw = (nt * 8 + g_) * 36 + s * 8 + tig;
                b0[nt] = Bb[bw];
                b1[nt] = Bb[bw + 4];
            }
            const uint32_t a_s = a_st + (uint32_t)(s * 32);
#pragma unroll
            for (int mt = 0; mt < 8; mt++) {
                uint32_t a0, a1, a2, a3;
                ldsm4(a0, a1, a2, a3, a_s + (uint32_t)(mt * 16 * XS_H * 2));
#pragma unroll
                for (int nt = 0; nt < 4; nt++)
                    mma_f16(acc[mt][nt], a0, a1, a2, a3, b0[nt], b1[nt]);
            }
        }
        buf = (buf + 1 == NBUF) ? 0 : buf + 1;

        if (tile == 3) {                         // layer boundary
            const int le = st >> 2;
            __syncthreads();                     // all reads of Xs done
#pragma unroll
            for (int mt = 0; mt < 8; mt++) {
#pragma unroll
                for (int nt = 0; nt < 4; nt++) {
                    const int c = wid * 32 + nt * 8 + 2 * tig;
                    const float bv0 = s_bias[le][c], bv1 = s_bias[le][c + 1];
                    const float v00 = fmaxf(acc[mt][nt][0] + bv0, 0.f);
                    const float v01 = fmaxf(acc[mt][nt][1] + bv1, 0.f);
                    const float v10 = fmaxf(acc[mt][nt][2] + bv0, 0.f);
                    const float v11 = fmaxf(acc[mt][nt][3] + bv1, 0.f);
                    const int r0 = mt * 16 + g_;
                    __half2* xw = (__half2*)Xs;
                    xw[r0 * 132 + wid * 16 + nt * 4 + tig]       = __floats2half2_rn(v00, v01);
                    xw[(r0 + 8) * 132 + wid * 16 + nt * 4 + tig] = __floats2half2_rn(v10, v11);
                    acc[mt][nt][0] = 0.f; acc[mt][nt][1] = 0.f;
                    acc[mt][nt][2] = 0.f; acc[mt][nt][3] = 0.f;
                }
            }
            __syncthreads();                     // writes visible before next layer
        }
    }

    // final 256->3 layer, fp32: thread = (row, k-half)
    {
        const int row = tid >> 1, hseg = tid & 1;
        const __half2* xw = (const __half2*)Xs + row * 132 + hseg * 64;
        float a0 = 0.f, a1 = 0.f, a2 = 0.f;
#pragma unroll 16
        for (int j = 0; j < 64; j++) {
            const float2 y = __half22float2(xw[j]);
            const float* wr = &s_w4[(hseg * 128 + 2 * j) * 3];
            a0 = fmaf(y.x, wr[0], fmaf(y.y, wr[3], a0));
            a1 = fmaf(y.x, wr[1], fmaf(y.y, wr[4], a1));
            a2 = fmaf(y.x, wr[2], fmaf(y.y, wr[5], a2));
        }
        s_red[row][hseg][0] = a0; s_red[row][hseg][1] = a1; s_red[row][hseg][2] = a2;
    }
    __syncthreads();

    // area-weighted combine + NCHW write
    if (tid < 96) {
        const int i = tid / 3;
        const int o = tid - 3 * (tid / 3);
        float v = 0.f;
#pragma unroll
        for (int t = 0; t < 4; t++) {
            const int row = t * 32 + i;
            const float p = s_b4[o] + s_red[row][0][o] + s_red[row][1][o];
            v += s_wt[t][i] * p;
        }
        out[((size_t)n * 3 + o) * 65536 + q0 + i] = v;
    }
}

} // anonymous namespace

extern "C" void kernel_launch(void* const* d_in, const int* in_sizes, int n_in,
                              void* d_out, int out_size)
{
    (void)in_sizes; (void)n_in; (void)out_size;
    const float* feat = (const float*)d_in[0];
    const float* w0 = (const float*)d_in[1];
    const float* b0 = (const float*)d_in[2];
    const float* w1 = (const float*)d_in[3];
    const float* b1 = (const float*)d_in[4];
    const float* w2 = (const float*)d_in[5];
    const float* b2 = (const float*)d_in[6];
    const float* w3 = (const float*)d_in[7];
    const float* b3 = (const float*)d_in[8];
    const float* w4 = (const float*)d_in[9];
    const float* b4 = (const float*)d_in[10];

    prep_w_kernel<<<(196608 + 255) / 256, 256>>>(w1, w2, w3);
    prep_proj_kernel<<<16384, 256>>>(feat, w0, b0);

    const size_t shmem = (size_t)(128 * XS_H + 8 * NBUF * BW_BUF) * sizeof(__half); // 178176 B
    cudaFuncSetAttribute(liif_hmma_kernel,
                         cudaFuncAttributeMaxDynamicSharedMemorySize, (int)shmem);
    dim3 grid(65536 / QT, 4);
    liif_hmma_kernel<<<grid, NTHR, shmem>>>(w0, w4, b1, b2, b3, b4, (float*)d_out);
}

// round 11
// speedup vs baseline: 1.0464x; 1.0100x over previous
#include <cuda_runtime.h>
#include <cuda_fp16.h>
#include <cstdint>

// LIIF render via fp16 HMMA (mma.sync m16n8k16) on sm_103.
// R11 = R8 (best: 1427us) + ping-pong X buffers: layer epilogue writes the
// OTHER X buffer, so the pre-epilogue __syncthreads disappears (1 barrier per
// layer boundary instead of 2; epilogue absorbs warp skew).
// M=128 per CTA, 256 threads / 8 warps, warp tile 128m x 32n, k-tile 64,
// warp-private double-buffered B strips, ldmatrix.x4 A-fragments.
// Layer-0 folded into precomputed projection P'.

namespace {

constexpr int NTHR    = 256;
constexpr int QT      = 32;
constexpr int XS_H    = 264;               // X row stride in halves (132 words)
constexpr int XBUF_H  = 128 * XS_H;        // halves per X buffer
constexpr int BW_H    = 72;                // B strip row stride in halves
constexpr int BW_BUF  = 32 * BW_H;         // halves per strip buffer (2304)
constexpr int NSTAGES = 12;                // 3 layers x 4 k-tiles of 64

__device__ __half g_wh[196608];            // w1..w3 transposed [l][n][k], fp16
__device__ float  g_proj[4 * 4096 * 256];  // P' = feat@w0f + b0 + cell-terms

__device__ __forceinline__ void cp16(uint32_t dst, const void* src) {
    asm volatile("cp.async.cg.shared.global [%0], [%1], 16;"
                 :: "r"(dst), "l"(src) : "memory");
}
__device__ __forceinline__ void cp_commit() {
    asm volatile("cp.async.commit_group;" ::: "memory");
}
template <int N>
__device__ __forceinline__ void cp_wait() {
    asm volatile("cp.async.wait_group %0;" :: "n"(N) : "memory");
}
__device__ __forceinline__ uint32_t smem_u32(const void* p) {
    uint32_t a;
    asm("{ .reg .u64 t; cvta.to.shared.u64 t, %1; cvt.u32.u64 %0, t; }"
        : "=r"(a) : "l"(p));
    return a;
}
__device__ __forceinline__ void ldsm4(uint32_t& r0, uint32_t& r1,
                                      uint32_t& r2, uint32_t& r3, uint32_t addr) {
    asm volatile("ldmatrix.sync.aligned.m8n8.x4.shared.b16 {%0,%1,%2,%3}, [%4];"
                 : "=r"(r0), "=r"(r1), "=r"(r2), "=r"(r3) : "r"(addr));
}
__device__ __forceinline__ void mma_f16(float c[4], uint32_t a0, uint32_t a1,
                                        uint32_t a2, uint32_t a3,
                                        uint32_t b0, uint32_t b1) {
    asm volatile(
        "mma.sync.aligned.m16n8k16.row.col.f32.f16.f16.f32 "
        "{%0,%1,%2,%3}, {%4,%5,%6,%7}, {%8,%9}, {%0,%1,%2,%3};"
        : "+f"(c[0]), "+f"(c[1]), "+f"(c[2]), "+f"(c[3])
        : "r"(a0), "r"(a1), "r"(a2), "r"(a3), "r"(b0), "r"(b1));
}

// ---------- prep 1: w1..w3 -> fp16, transposed to [l][n][k] ----------
__global__ void prep_w_kernel(const float* __restrict__ w1, const float* __restrict__ w2,
                              const float* __restrict__ w3) {
    const int idx = blockIdx.x * blockDim.x + threadIdx.x;
    if (idx >= 196608) return;
    const int l = idx >> 16;
    const int rem = idx & 65535;
    const int nn = rem >> 8, k = rem & 255;
    const float* w = (l == 0) ? w1 : (l == 1) ? w2 : w3;
    g_wh[idx] = __float2half_rn(w[k * 256 + nn]);
}

// ---------- prep 2: P'[n][idx][c] (fp32, validated R4/R5) ----------
__global__ void prep_proj_kernel(const float* __restrict__ feat,
                                 const float* __restrict__ w0,
                                 const float* __restrict__ b0) {
    __shared__ float sf[64];
    const int blk = blockIdx.x;
    const int n   = blk >> 12;
    const int idx = blk & 4095;
    const int c   = threadIdx.x;
    if (c < 64) sf[c] = feat[((size_t)n * 64 + c) * 4096 + idx];
    __syncthreads();
    float acc = b0[c] + 0.5f * (w0[66 * 256 + c] + w0[67 * 256 + c]);
#pragma unroll 8
    for (int ch = 0; ch < 64; ch++)
        acc = fmaf(sf[ch], w0[ch * 256 + c], acc);
    g_proj[(size_t)blk * 256 + c] = acc;
}

// ---------- main kernel ----------
__global__ __launch_bounds__(NTHR, 1)
void liif_hmma_kernel(const float* __restrict__ w0, const float* __restrict__ w4,
                      const float* __restrict__ b1, const float* __restrict__ b2,
                      const float* __restrict__ b3, const float* __restrict__ b4,
                      float* __restrict__ out)
{
    extern __shared__ __half smem_h[];
    __half* X0 = smem_h;                         // 128 x 264 halves
    __half* X1 = smem_h + XBUF_H;                // 128 x 264 halves
    __half* Bs = smem_h + 2 * XBUF_H;            // 8 warps x 2 bufs x 2304 halves
    const uint32_t xs_u = smem_u32(X0);
    const uint32_t bs_u = smem_u32(Bs);

    __shared__ float s_bias[3][256];
    __shared__ float s_w0r[2][256];
    __shared__ float s_w4[772];
    __shared__ float s_b4[3];
    __shared__ int   s_idx[4][QT];
    __shared__ float s_rel[4][2][QT];
    __shared__ float s_wt[4][QT];
    __shared__ float s_red[128][2][3];

    const int tid  = threadIdx.x;
    const int wid  = tid >> 5;
    const int lane = tid & 31;
    const int g_   = lane >> 2, tig = lane & 3;
    const int n    = blockIdx.y;
    const int q0   = blockIdx.x * QT;

    // per-warp B strip copy: stage st (layer st>>2, tile st&3) -> buffer buf
    auto prefetch = [&](int buf, int st) {
        const int l2 = st >> 2, t2 = st & 3;
        const uint32_t dst0 = bs_u + (uint32_t)(wid * 2 * BW_BUF + buf * BW_BUF) * 2u;
#pragma unroll
        for (int j = 0; j < 8; j++) {
            const int e = lane + 32 * j;
            const int row = e >> 3, ch = e & 7;          // n-row 0..31, 16B chunk 0..7
            const __half* src = g_wh + (((l2 * 256 + wid * 32 + row) << 8) + t2 * 64 + ch * 8);
            cp16(dst0 + (uint32_t)(row * BW_H + ch * 8) * 2u, src);
        }
        cp_commit();
    };

    prefetch(0, 0);     // stage 0 in flight during setup

    for (int i = tid; i < 256; i += NTHR) {
        s_bias[0][i] = b1[i]; s_bias[1][i] = b2[i]; s_bias[2][i] = b3[i];
        s_w0r[0][i] = w0[64 * 256 + i]; s_w0r[1][i] = w0[65 * 256 + i];
    }
    for (int i = tid; i < 768; i += NTHR) s_w4[i] = w4[i];
    if (tid < 3) s_b4[tid] = b4[tid];

    // per-query geometry (validated R1/R3)
    if (tid < QT) {
        const int q = q0 + tid;
        const int yq = q >> 8, xq = q & 255;
        const float c0 = (2.f * (float)yq + 1.f) * (1.f / 256.f) - 1.f;
        const float c1 = (2.f * (float)xq + 1.f) * (1.f / 256.f) - 1.f;
        const float lo = (float)(-1.0 + 1e-6), hi = (float)(1.0 - 1e-6);
        float areas[4];
#pragma unroll
        for (int t = 0; t < 4; t++) {
            const double vx = (t < 2) ? -1.0 : 1.0;
            const double vy = (t & 1) ? 1.0 : -1.0;
            const float shx = (float)(vx * (1.0 / 64.0) + 1e-6);
            const float shy = (float)(vy * (1.0 / 64.0) + 1e-6);
            const float cc0 = fminf(fmaxf(c0 + shx, lo), hi);
            const float cc1 = fminf(fmaxf(c1 + shy, lo), hi);
            int iy = (int)rintf(((cc0 + 1.f) * 64.f - 1.f) * 0.5f);
            int ix = (int)rintf(((cc1 + 1.f) * 64.f - 1.f) * 0.5f);
            iy = min(max(iy, 0), 63); ix = min(max(ix, 0), 63);
            const float qc0 = (2.f * (float)iy + 1.f) * (1.f / 64.f) - 1.f;
            const float qc1 = (2.f * (float)ix + 1.f) * (1.f / 64.f) - 1.f;
            const float r0 = (c0 - qc0) * 64.f;
            const float r1 = (c1 - qc1) * 64.f;
            s_idx[t][tid] = iy * 64 + ix;
            s_rel[t][0][tid] = r0; s_rel[t][1][tid] = r1;
            areas[t] = fabsf(r0 * r1) + 1e-9f;
        }
        const float tot = areas[0] + areas[1] + areas[2] + areas[3];
#pragma unroll
        for (int t = 0; t < 4; t++) s_wt[t][tid] = areas[3 - t] / tot;
    }
    __syncthreads();

    // h0 build into X0: thread = (row, 128-col half); fp32 math, round to fp16
    {
        const int row = tid >> 1, hseg = tid & 1;
        const int t = row >> 5, i = row & 31;
        const int idx = s_idx[t][i];
        const float r0 = s_rel[t][0][i], r1 = s_rel[t][1][i];
        const float4* pp = (const float4*)(g_proj + (((size_t)n << 12) + idx) * 256)
                           + hseg * 32;
        __half2* xw = (__half2*)X0 + row * 132 + hseg * 64;
#pragma unroll
        for (int j = 0; j < 32; j++) {
            const float4 p = pp[j];
            const int c = hseg * 128 + j * 4;
            const float v0 = fmaf(r0, s_w0r[0][c],     fmaf(r1, s_w0r[1][c],     p.x));
            const float v1 = fmaf(r0, s_w0r[0][c + 1], fmaf(r1, s_w0r[1][c + 1], p.y));
            const float v2 = fmaf(r0, s_w0r[0][c + 2], fmaf(r1, s_w0r[1][c + 2], p.z));
            const float v3 = fmaf(r0, s_w0r[0][c + 3], fmaf(r1, s_w0r[1][c + 3], p.w));
            xw[j * 2]     = __floats2half2_rn(fmaxf(v0, 0.f), fmaxf(v1, 0.f));
            xw[j * 2 + 1] = __floats2half2_rn(fmaxf(v2, 0.f), fmaxf(v3, 0.f));
        }
    }
    __syncthreads();

    // ldmatrix per-lane A base: row = lane&15, k-halves add = (lane>>4)*8
    const int lrow = lane & 15;
    const int kadd = (lane >> 4) << 3;
    const uint32_t a_lane = xs_u + (uint32_t)(lrow * XS_H + kadd) * 2u;

    const uint32_t* Bw = (const uint32_t*)(Bs + wid * 2 * BW_BUF);

    float acc[8][4][4];
#pragma unroll
    for (int mt = 0; mt < 8; mt++)
#pragma unroll
        for (int nt = 0; nt < 4; nt++)
#pragma unroll
            for (int r = 0; r < 4; r++) acc[mt][nt][r] = 0.f;

    int buf = 0;
#pragma unroll 1
    for (int st = 0; st < NSTAGES; st++) {
        const int tile = st & 3;
        const int le   = st >> 2;                // layer 0..2
        const int rpar = le & 1;                 // read buffer: L1:X0, L2:X1, L3:X0

        if (st + 1 < NSTAGES) { prefetch(buf ^ 1, st + 1); cp_wait<1>(); }
        else                  { cp_wait<0>(); }
        // no __syncthreads: B strips are warp-private, X read buffer is stable

        const uint32_t* Bb = Bw + buf * (BW_BUF / 2);
        const uint32_t a_st = a_lane + (uint32_t)rpar * (XBUF_H * 2u)
                            + (uint32_t)(tile * 64) * 2u;            // halves -> bytes

#pragma unroll
        for (int s = 0; s < 4; s++) {            // four k16 steps per 64-k tile
            uint32_t b0[4], b1[4];
#pragma unroll
            for (int nt = 0; nt < 4; nt++) {
                const int bw = (nt * 8 + g_) * 36 + s * 8 + tig;
                b0[nt] = Bb[bw];
                b1[nt] = Bb[bw + 4];
            }
            const uint32_t a_s = a_st + (uint32_t)(s * 32);
#pragma unroll
            for (int mt = 0; mt < 8; mt++) {
                uint32_t a0, a1, a2, a3;
                ldsm4(a0, a1, a2, a3, a_s + (uint32_t)(mt * 16 * XS_H * 2));
#pragma unroll
                for (int nt = 0; nt < 4; nt++)
                    mma_f16(acc[mt][nt], a0, a1, a2, a3, b0[nt], b1[nt]);
            }
        }
        buf ^= 1;

        if (tile == 3) {
            // epilogue writes the OTHER X buffer: no pre-barrier needed.
            __half2* xw = (__half2*)(smem_h + (size_t)(rpar ^ 1) * XBUF_H);
#pragma unroll
            for (int mt = 0; mt < 8; mt++) {
#pragma unroll
                for (int nt = 0; nt < 4; nt++) {
                    const int c = wid * 32 + nt * 8 + 2 * tig;
                    const float bv0 = s_bias[le][c], bv1 = s_bias[le][c + 1];
                    const float v00 = fmaxf(acc[mt][nt][0] + bv0, 0.f);
                    const float v01 = fmaxf(acc[mt][nt][1] + bv1, 0.f);
                    const float v10 = fmaxf(acc[mt][nt][2] + bv0, 0.f);
                    const float v11 = fmaxf(acc[mt][nt][3] + bv1, 0.f);
                    const int r0 = mt * 16 + g_;
                    xw[r0 * 132 + wid * 16 + nt * 4 + tig]       = __floats2half2_rn(v00, v01);
                    xw[(r0 + 8) * 132 + wid * 16 + nt * 4 + tig] = __floats2half2_rn(v10, v11);
                    acc[mt][nt][0] = 0.f; acc[mt][nt][1] = 0.f;
                    acc[mt][nt][2] = 0.f; acc[mt][nt][3] = 0.f;
                }
            }
            __syncthreads();                     // writes visible before next layer
        }
    }

    // final 256->3 layer, fp32, reads X1: thread = (row, k-half)
    {
        const int row = tid >> 1, hseg = tid & 1;
        const __half2* xw = (const __half2*)X1 + row * 132 + hseg * 64;
        float a0 = 0.f, a1 = 0.f, a2 = 0.f;
#pragma unroll 16
        for (int j = 0; j < 64; j++) {
            const float2 y = __half22float2(xw[j]);
            const float* wr = &s_w4[(hseg * 128 + 2 * j) * 3];
            a0 = fmaf(y.x, wr[0], fmaf(y.y, wr[3], a0));
            a1 = fmaf(y.x, wr[1], fmaf(y.y, wr[4], a1));
            a2 = fmaf(y.x, wr[2], fmaf(y.y, wr[5], a2));
        }
        s_red[row][hseg][0] = a0; s_red[row][hseg][1] = a1; s_red[row][hseg][2] = a2;
    }
    __syncthreads();

    // area-weighted combine + NCHW write
    if (tid < 96) {
        const int i = tid / 3;
        const int o = tid - 3 * (tid / 3);
        float v = 0.f;
#pragma unroll
        for (int t = 0; t < 4; t++) {
            const int row = t * 32 + i;
            const float p = s_b4[o] + s_red[row][0][o] + s_red[row][1][o];
            v += s_wt[t][i] * p;
        }
        out[((size_t)n * 3 + o) * 65536 + q0 + i] = v;
    }
}

} // anonymous namespace

extern "C" void kernel_launch(void* const* d_in, const int* in_sizes, int n_in,
                              void* d_out, int out_size)
{
    (void)in_sizes; (void)n_in; (void)out_size;
    const float* feat = (const float*)d_in[0];
    const float* w0 = (const float*)d_in[1];
    const float* b0 = (const float*)d_in[2];
    const float* w1 = (const float*)d_in[3];
    const float* b1 = (const float*)d_in[4];
    const float* w2 = (const float*)d_in[5];
    const float* b2 = (const float*)d_in[6];
    const float* w3 = (const float*)d_in[7];
    const float* b3 = (const float*)d_in[8];
    const float* w4 = (const float*)d_in[9];
    const float* b4 = (const float*)d_in[10];

    prep_w_kernel<<<(196608 + 255) / 256, 256>>>(w1, w2, w3);
    prep_proj_kernel<<<16384, 256>>>(feat, w0, b0);

    const size_t shmem = (size_t)(2 * XBUF_H + 8 * 2 * BW_BUF) * sizeof(__half); // 208896 B
    cudaFuncSetAttribute(liif_hmma_kernel,
                         cudaFuncAttributeMaxDynamicSharedMemorySize, (int)shmem);
    dim3 grid(65536 / QT, 4);
    liif_hmma_kernel<<<grid, NTHR, shmem>>>(w0, w4, b1, b2, b3, b4, (float*)d_out);
}

// round 12
// speedup vs baseline: 1.0956x; 1.0470x over previous
#include <cuda_runtime.h>
#include <cuda_fp16.h>
#include <cstdint>

// LIIF render via fp16 HMMA (mma.sync m16n8k16) on sm_103.
// R12 = R8 (best: 1427us) + optimized P' path:
//   - prep_proj tiled: w0 staged in smem once per 16 cells (L2 traffic /14)
//   - P' stored fp16 (halves prep writes + main-kernel h0 reads)
// Main kernel mainloop identical to R8: M=128, 8 warps, 128m x 32n warp
// tiles, k-tile 64, warp-private double-buffered B strips, ldmatrix.x4.

namespace {

constexpr int NTHR    = 256;
constexpr int QT      = 32;
constexpr int XS_H    = 264;               // X row stride in halves (132 words)
constexpr int BW_H    = 72;                // B strip row stride in halves
constexpr int BW_BUF  = 32 * BW_H;         // halves per strip buffer (2304)
constexpr int NSTAGES = 12;                // 3 layers x 4 k-tiles of 64

__device__ __half g_wh[196608];            // w1..w3 transposed [l][n][k], fp16
__device__ __half g_proj_h[4 * 4096 * 256];// P' = feat@w0f + b0 + cell-terms (fp16)

__device__ __forceinline__ void cp16(uint32_t dst, const void* src) {
    asm volatile("cp.async.cg.shared.global [%0], [%1], 16;"
                 :: "r"(dst), "l"(src) : "memory");
}
__device__ __forceinline__ void cp_commit() {
    asm volatile("cp.async.commit_group;" ::: "memory");
}
template <int N>
__device__ __forceinline__ void cp_wait() {
    asm volatile("cp.async.wait_group %0;" :: "n"(N) : "memory");
}
__device__ __forceinline__ uint32_t smem_u32(const void* p) {
    uint32_t a;
    asm("{ .reg .u64 t; cvta.to.shared.u64 t, %1; cvt.u32.u64 %0, t; }"
        : "=r"(a) : "l"(p));
    return a;
}
__device__ __forceinline__ void ldsm4(uint32_t& r0, uint32_t& r1,
                                      uint32_t& r2, uint32_t& r3, uint32_t addr) {
    asm volatile("ldmatrix.sync.aligned.m8n8.x4.shared.b16 {%0,%1,%2,%3}, [%4];"
                 : "=r"(r0), "=r"(r1), "=r"(r2), "=r"(r3) : "r"(addr));
}
__device__ __forceinline__ void mma_f16(float c[4], uint32_t a0, uint32_t a1,
                                        uint32_t a2, uint32_t a3,
                                        uint32_t b0, uint32_t b1) {
    asm volatile(
        "mma.sync.aligned.m16n8k16.row.col.f32.f16.f16.f32 "
        "{%0,%1,%2,%3}, {%4,%5,%6,%7}, {%8,%9}, {%0,%1,%2,%3};"
        : "+f"(c[0]), "+f"(c[1]), "+f"(c[2]), "+f"(c[3])
        : "r"(a0), "r"(a1), "r"(a2), "r"(a3), "r"(b0), "r"(b1));
}

// ---------- prep 1: w1..w3 -> fp16, transposed to [l][n][k] ----------
__global__ void prep_w_kernel(const float* __restrict__ w1, const float* __restrict__ w2,
                              const float* __restrict__ w3) {
    const int idx = blockIdx.x * blockDim.x + threadIdx.x;
    if (idx >= 196608) return;
    const int l = idx >> 16;
    const int rem = idx & 65535;
    const int nn = rem >> 8, k = rem & 255;
    const float* w = (l == 0) ? w1 : (l == 1) ? w2 : w3;
    g_wh[idx] = __float2half_rn(w[k * 256 + nn]);
}

// ---------- prep 2: tiled P' build, fp16 output ----------
// block = 16 cells of one image; w0 (64x256) staged in smem once per block.
__global__ __launch_bounds__(256, 1)
void prep_proj_kernel(const float* __restrict__ feat,
                      const float* __restrict__ w0,
                      const float* __restrict__ b0) {
    extern __shared__ float ps[];
    float* sw = ps;                 // 64 x 256
    float* bf = ps + 16384;         // 256
    float* sf = ps + 16640;         // 16 cells x 64 ch
    const int blk  = blockIdx.x;    // 0..1023
    const int n    = blk >> 8;
    const int idx0 = (blk & 255) * 16;
    const int c    = threadIdx.x;   // output column 0..255

    for (int r = 0; r < 64; r++) sw[r * 256 + c] = w0[r * 256 + c];
    bf[c] = b0[c] + 0.5f * (w0[66 * 256 + c] + w0[67 * 256 + c]);
    for (int e = c; e < 1024; e += 256) {
        const int ch = e >> 4, ci = e & 15;
        sf[ci * 64 + ch] = feat[(((size_t)n * 64 + ch) << 12) + idx0 + ci];
    }
    __syncthreads();

#pragma unroll 1
    for (int ci = 0; ci < 16; ci++) {
        float acc = bf[c];
        const float* sfr = sf + ci * 64;
#pragma unroll 16
        for (int ch = 0; ch < 64; ch++)
            acc = fmaf(sfr[ch], sw[ch * 256 + c], acc);
        g_proj_h[(((size_t)n << 12) + idx0 + ci) * 256 + c] = __float2half_rn(acc);
    }
}

// ---------- main kernel ----------
__global__ __launch_bounds__(NTHR, 1)
void liif_hmma_kernel(const float* __restrict__ w0, const float* __restrict__ w4,
                      const float* __restrict__ b1, const float* __restrict__ b2,
                      const float* __restrict__ b3, const float* __restrict__ b4,
                      float* __restrict__ out)
{
    extern __shared__ __half smem_h[];
    __half* Xs = smem_h;                         // 128 x 264 halves
    __half* Bs = smem_h + 128 * XS_H;            // 8 warps x 2 bufs x 2304 halves
    const uint32_t xs_u = smem_u32(Xs);
    const uint32_t bs_u = smem_u32(Bs);

    __shared__ float s_bias[3][256];
    __shared__ float s_w0r[2][256];
    __shared__ float s_w4[772];
    __shared__ float s_b4[3];
    __shared__ int   s_idx[4][QT];
    __shared__ float s_rel[4][2][QT];
    __shared__ float s_wt[4][QT];
    __shared__ float s_red[128][2][3];

    const int tid  = threadIdx.x;
    const int wid  = tid >> 5;
    const int lane = tid & 31;
    const int g_   = lane >> 2, tig = lane & 3;
    const int n    = blockIdx.y;
    const int q0   = blockIdx.x * QT;

    // per-warp B strip copy: stage st (layer st>>2, tile st&3) -> buffer buf
    auto prefetch = [&](int buf, int st) {
        const int l2 = st >> 2, t2 = st & 3;
        const uint32_t dst0 = bs_u + (uint32_t)(wid * 2 * BW_BUF + buf * BW_BUF) * 2u;
#pragma unroll
        for (int j = 0; j < 8; j++) {
            const int e = lane + 32 * j;
            const int row = e >> 3, ch = e & 7;          // n-row 0..31, 16B chunk 0..7
            const __half* src = g_wh + (((l2 * 256 + wid * 32 + row) << 8) + t2 * 64 + ch * 8);
            cp16(dst0 + (uint32_t)(row * BW_H + ch * 8) * 2u, src);
        }
        cp_commit();
    };

    prefetch(0, 0);     // stage 0 in flight during setup

    for (int i = tid; i < 256; i += NTHR) {
        s_bias[0][i] = b1[i]; s_bias[1][i] = b2[i]; s_bias[2][i] = b3[i];
        s_w0r[0][i] = w0[64 * 256 + i]; s_w0r[1][i] = w0[65 * 256 + i];
    }
    for (int i = tid; i < 768; i += NTHR) s_w4[i] = w4[i];
    if (tid < 3) s_b4[tid] = b4[tid];

    // per-query geometry (validated R1/R3)
    if (tid < QT) {
        const int q = q0 + tid;
        const int yq = q >> 8, xq = q & 255;
        const float c0 = (2.f * (float)yq + 1.f) * (1.f / 256.f) - 1.f;
        const float c1 = (2.f * (float)xq + 1.f) * (1.f / 256.f) - 1.f;
        const float lo = (float)(-1.0 + 1e-6), hi = (float)(1.0 - 1e-6);
        float areas[4];
#pragma unroll
        for (int t = 0; t < 4; t++) {
            const double vx = (t < 2) ? -1.0 : 1.0;
            const double vy = (t & 1) ? 1.0 : -1.0;
            const float shx = (float)(vx * (1.0 / 64.0) + 1e-6);
            const float shy = (float)(vy * (1.0 / 64.0) + 1e-6);
            const float cc0 = fminf(fmaxf(c0 + shx, lo), hi);
            const float cc1 = fminf(fmaxf(c1 + shy, lo), hi);
            int iy = (int)rintf(((cc0 + 1.f) * 64.f - 1.f) * 0.5f);
            int ix = (int)rintf(((cc1 + 1.f) * 64.f - 1.f) * 0.5f);
            iy = min(max(iy, 0), 63); ix = min(max(ix, 0), 63);
            const float qc0 = (2.f * (float)iy + 1.f) * (1.f / 64.f) - 1.f;
            const float qc1 = (2.f * (float)ix + 1.f) * (1.f / 64.f) - 1.f;
            const float r0 = (c0 - qc0) * 64.f;
            const float r1 = (c1 - qc1) * 64.f;
            s_idx[t][tid] = iy * 64 + ix;
            s_rel[t][0][tid] = r0; s_rel[t][1][tid] = r1;
            areas[t] = fabsf(r0 * r1) + 1e-9f;
        }
        const float tot = areas[0] + areas[1] + areas[2] + areas[3];
#pragma unroll
        for (int t = 0; t < 4; t++) s_wt[t][tid] = areas[3 - t] / tot;
    }
    __syncthreads();

    // h0 build: thread = (row, 128-col half); P' fp16 -> fp32 math -> fp16
    {
        const int row = tid >> 1, hseg = tid & 1;
        const int t = row >> 5, i = row & 31;
        const int idx = s_idx[t][i];
        const float r0 = s_rel[t][0][i], r1 = s_rel[t][1][i];
        const uint4* pp = (const uint4*)(g_proj_h + (((size_t)n << 12) + idx) * 256
                                         + hseg * 128);
        __half2* xw = (__half2*)Xs + row * 132 + hseg * 64;
#pragma unroll
        for (int j = 0; j < 16; j++) {
            const uint4 q = pp[j];
            uint32_t w[4] = {q.x, q.y, q.z, q.w};
            const int cb = hseg * 128 + j * 8;
#pragma unroll
            for (int u = 0; u < 4; u++) {
                const float2 p = __half22float2(*(const __half2*)&w[u]);
                const int c = cb + 2 * u;
                const float v0 = fmaf(r0, s_w0r[0][c],     fmaf(r1, s_w0r[1][c],     p.x));
                const float v1 = fmaf(r0, s_w0r[0][c + 1], fmaf(r1, s_w0r[1][c + 1], p.y));
                xw[j * 4 + u] = __floats2half2_rn(fmaxf(v0, 0.f), fmaxf(v1, 0.f));
            }
        }
    }
    __syncthreads();

    // ldmatrix per-lane A base: row = lane&15, k-halves add = (lane>>4)*8
    const int lrow = lane & 15;
    const int kadd = (lane >> 4) << 3;
    const uint32_t a_lane = xs_u + (uint32_t)(lrow * XS_H + kadd) * 2u;

    const uint32_t* Bw = (const uint32_t*)(Bs + wid * 2 * BW_BUF);

    float acc[8][4][4];
#pragma unroll
    for (int mt = 0; mt < 8; mt++)
#pragma unroll
        for (int nt = 0; nt < 4; nt++)
#pragma unroll
            for (int r = 0; r < 4; r++) acc[mt][nt][r] = 0.f;

    int buf = 0;
#pragma unroll 1
    for (int st = 0; st < NSTAGES; st++) {
        const int tile = st & 3;

        if (st + 1 < NSTAGES) { prefetch(buf ^ 1, st + 1); cp_wait<1>(); }
        else                  { cp_wait<0>(); }
        // no __syncthreads: B strips are warp-private, Xs is read-only here

        const uint32_t* Bb = Bw + buf * (BW_BUF / 2);
        const uint32_t a_st = a_lane + (uint32_t)(tile * 64) * 2u;   // halves -> bytes

#pragma unroll
        for (int s = 0; s < 4; s++) {            // four k16 steps per 64-k tile
            uint32_t b0[4], b1[4];
#pragma unroll
            for (int nt = 0; nt < 4; nt++) {
                const int bw = (nt * 8 + g_) * 36 + s * 8 + tig;
                b0[nt] = Bb[bw];
                b1[nt] = Bb[bw + 4];
            }
            const uint32_t a_s = a_st + (uint32_t)(s * 32);
#pragma unroll
            for (int mt = 0; mt < 8; mt++) {
                uint32_t a0, a1, a2, a3;
                ldsm4(a0, a1, a2, a3, a_s + (uint32_t)(mt * 16 * XS_H * 2));
#pragma unroll
                for (int nt = 0; nt < 4; nt++)
                    mma_f16(acc[mt][nt], a0, a1, a2, a3, b0[nt], b1[nt]);
            }
        }
        buf ^= 1;

        if (tile == 3) {                         // layer boundary
            const int le = st >> 2;
            __syncthreads();                     // all reads of Xs done
#pragma unroll
            for (int mt = 0; mt < 8; mt++) {
#pragma unroll
                for (int nt = 0; nt < 4; nt++) {
                    const int c = wid * 32 + nt * 8 + 2 * tig;
                    const float bv0 = s_bias[le][c], bv1 = s_bias[le][c + 1];
                    const float v00 = fmaxf(acc[mt][nt][0] + bv0, 0.f);
                    const float v01 = fmaxf(acc[mt][nt][1] + bv1, 0.f);
                    const float v10 = fmaxf(acc[mt][nt][2] + bv0, 0.f);
                    const float v11 = fmaxf(acc[mt][nt][3] + bv1, 0.f);
                    const int r0 = mt * 16 + g_;
                    __half2* xw = (__half2*)Xs;
                    xw[r0 * 132 + wid * 16 + nt * 4 + tig]       = __floats2half2_rn(v00, v01);
                    xw[(r0 + 8) * 132 + wid * 16 + nt * 4 + tig] = __floats2half2_rn(v10, v11);
                    acc[mt][nt][0] = 0.f; acc[mt][nt][1] = 0.f;
                    acc[mt][nt][2] = 0.f; acc[mt][nt][3] = 0.f;
                }
            }
            __syncthreads();                     // writes visible before next layer
        }
    }

    // final 256->3 layer, fp32: thread = (row, k-half)
    {
        const int row = tid >> 1, hseg = tid & 1;
        const __half2* xw = (const __half2*)Xs + row * 132 + hseg * 64;
        float a0 = 0.f, a1 = 0.f, a2 = 0.f;
#pragma unroll 16
        for (int j = 0; j < 64; j++) {
            const float2 y = __half22float2(xw[j]);
            const float* wr = &s_w4[(hseg * 128 + 2 * j) * 3];
            a0 = fmaf(y.x, wr[0], fmaf(y.y, wr[3], a0));
            a1 = fmaf(y.x, wr[1], fmaf(y.y, wr[4], a1));
            a2 = fmaf(y.x, wr[2], fmaf(y.y, wr[5], a2));
        }
        s_red[row][hseg][0] = a0; s_red[row][hseg][1] = a1; s_red[row][hseg][2] = a2;
    }
    __syncthreads();

    // area-weighted combine + NCHW write
    if (tid < 96) {
        const int i = tid / 3;
        const int o = tid - 3 * (tid / 3);
        float v = 0.f;
#pragma unroll
        for (int t = 0; t < 4; t++) {
            const int row = t * 32 + i;
            const float p = s_b4[o] + s_red[row][0][o] + s_red[row][1][o];
            v += s_wt[t][i] * p;
        }
        out[((size_t)n * 3 + o) * 65536 + q0 + i] = v;
    }
}

} // anonymous namespace

extern "C" void kernel_launch(void* const* d_in, const int* in_sizes, int n_in,
                              void* d_out, int out_size)
{
    (void)in_sizes; (void)n_in; (void)out_size;
    const float* feat = (const float*)d_in[0];
    const float* w0 = (const float*)d_in[1];
    const float* b0 = (const float*)d_in[2];
    const float* w1 = (const float*)d_in[3];
    const float* b1 = (const float*)d_in[4];
    const float* w2 = (const float*)d_in[5];
    const float* b2 = (const float*)d_in[6];
    const float* w3 = (const float*)d_in[7];
    const float* b3 = (const float*)d_in[8];
    const float* w4 = (const float*)d_in[9];
    const float* b4 = (const float*)d_in[10];

    prep_w_kernel<<<(196608 + 255) / 256, 256>>>(w1, w2, w3);

    const size_t proj_shmem = (16384 + 256 + 1024) * sizeof(float);  // 70656 B
    cudaFuncSetAttribute(prep_proj_kernel,
                         cudaFuncAttributeMaxDynamicSharedMemorySize, (int)proj_shmem);
    prep_proj_kernel<<<1024, 256, proj_shmem>>>(feat, w0, b0);

    const size_t shmem = (size_t)(128 * XS_H + 8 * 2 * BW_BUF) * sizeof(__half); // 141312 B
    cudaFuncSetAttribute(liif_hmma_kernel,
                         cudaFuncAttributeMaxDynamicSharedMemorySize, (int)shmem);
    dim3 grid(65536 / QT, 4);
    liif_hmma_kernel<<<grid, NTHR, shmem>>>(w0, w4, b1, b2, b3, b4, (float*)d_out);
}

// round 13
// speedup vs baseline: 1.1307x; 1.0321x over previous
#include <cuda_runtime.h>
#include <cuda_fp16.h>
#include <cstdint>

// LIIF render via fp16 HMMA (mma.sync m16n8k16) on sm_103.
// R13 = R12 (best: 1372us) with:
//   - prep_proj on tensor cores (fp16 HMMA, same fragment layout as mainloop)
//   - geometry parallelized across 128 threads (one corner each)
// Main kernel mainloop/epilogue identical to R12.

namespace {

constexpr int NTHR    = 256;
constexpr int QT      = 32;
constexpr int XS_H    = 264;               // X row stride in halves (132 words)
constexpr int BW_H    = 72;                // B strip row stride in halves
constexpr int BW_BUF  = 32 * BW_H;         // halves per strip buffer (2304)
constexpr int NSTAGES = 12;                // 3 layers x 4 k-tiles of 64

__device__ __half g_wh[196608];            // w1..w3 transposed [l][n][k], fp16
__device__ __half g_w0h[16384];            // w0 feature rows transposed [n][k<64], fp16
__device__ __half g_proj_h[4 * 4096 * 256];// P' fp16

__device__ __forceinline__ void cp16(uint32_t dst, const void* src) {
    asm volatile("cp.async.cg.shared.global [%0], [%1], 16;"
                 :: "r"(dst), "l"(src) : "memory");
}
__device__ __forceinline__ void cp_commit() {
    asm volatile("cp.async.commit_group;" ::: "memory");
}
template <int N>
__device__ __forceinline__ void cp_wait() {
    asm volatile("cp.async.wait_group %0;" :: "n"(N) : "memory");
}
__device__ __forceinline__ uint32_t smem_u32(const void* p) {
    uint32_t a;
    asm("{ .reg .u64 t; cvta.to.shared.u64 t, %1; cvt.u32.u64 %0, t; }"
        : "=r"(a) : "l"(p));
    return a;
}
__device__ __forceinline__ void ldsm4(uint32_t& r0, uint32_t& r1,
                                      uint32_t& r2, uint32_t& r3, uint32_t addr) {
    asm volatile("ldmatrix.sync.aligned.m8n8.x4.shared.b16 {%0,%1,%2,%3}, [%4];"
                 : "=r"(r0), "=r"(r1), "=r"(r2), "=r"(r3) : "r"(addr));
}
__device__ __forceinline__ void mma_f16(float c[4], uint32_t a0, uint32_t a1,
                                        uint32_t a2, uint32_t a3,
                                        uint32_t b0, uint32_t b1) {
    asm volatile(
        "mma.sync.aligned.m16n8k16.row.col.f32.f16.f16.f32 "
        "{%0,%1,%2,%3}, {%4,%5,%6,%7}, {%8,%9}, {%0,%1,%2,%3};"
        : "+f"(c[0]), "+f"(c[1]), "+f"(c[2]), "+f"(c[3])
        : "r"(a0), "r"(a1), "r"(a2), "r"(a3), "r"(b0), "r"(b1));
}

// ---------- prep 1: weights -> fp16 transposed ----------
__global__ void prep_w_kernel(const float* __restrict__ w1, const float* __restrict__ w2,
                              const float* __restrict__ w3, const float* __restrict__ w0) {
    const int idx = blockIdx.x * blockDim.x + threadIdx.x;
    if (idx < 196608) {
        const int l = idx >> 16;
        const int rem = idx & 65535;
        const int nn = rem >> 8, k = rem & 255;
        const float* w = (l == 0) ? w1 : (l == 1) ? w2 : w3;
        g_wh[idx] = __float2half_rn(w[k * 256 + nn]);
    } else if (idx < 196608 + 16384) {
        const int e = idx - 196608;
        const int nn = e >> 6, k = e & 63;
        g_w0h[e] = __float2half_rn(w0[k * 256 + nn]);
    }
}

// ---------- prep 2: P' via fp16 HMMA ----------
// block = 128 cells of one image: [128,64] x [64,256] + bias terms -> fp16 P'.
__global__ __launch_bounds__(256, 1)
void prep_proj_kernel(const float* __restrict__ feat,
                      const float* __restrict__ w0,
                      const float* __restrict__ b0) {
    extern __shared__ __half pps[];
    __half* A   = pps;                        // 128 cells x 72 halves (k-major)
    __half* Bst = pps + 128 * 72;             // 8 warps x 32 n x 72 halves
    float*  bf  = (float*)(pps + 128 * 72 + 8 * 32 * 72);   // 256 bias
    const uint32_t a_u = smem_u32(A);

    const int blk   = blockIdx.x;             // 0..127
    const int n     = blk >> 5;
    const int cell0 = (blk & 31) << 7;
    const int tid   = threadIdx.x;
    const int wid   = tid >> 5;
    const int lane  = tid & 31;
    const int g_    = lane >> 2, tig = lane & 3;

    // B strip: warp wid owns n-cols wid*32..+31 of w0 (k<64), 16B chunks
    {
        uint4* bd = (uint4*)(Bst + wid * 32 * 72);
        const uint4* bsrc = (const uint4*)(g_w0h + wid * 32 * 64);
#pragma unroll
        for (int j = 0; j < 8; j++) {
            const int e = lane + 32 * j;                 // 0..255
            const int row = e >> 3, ch = e & 7;          // n-row, 16B chunk (8 halves)
            bd[(row * 72 + ch * 8) >> 3] = bsrc[row * 8 + ch];
        }
    }
    // bias: b0 + 0.5*(w0[66]+w0[67])
    bf[tid] = b0[tid] + 0.5f * (w0[66 * 256 + tid] + w0[67 * 256 + tid]);
    // A: feat[n][ch][cell0..+127] -> A[cell][ch] fp16 (transposed store)
#pragma unroll
    for (int j = 0; j < 8; j++) {
        const int e = tid + 256 * j;                     // 0..2047 float4 elems
        const int ch = e >> 5, c4 = e & 31;
        const float4 v = ((const float4*)feat)[(((size_t)n * 64 + ch) << 10)
                                               + (cell0 >> 2) + c4];
        A[(4 * c4 + 0) * 72 + ch] = __float2half_rn(v.x);
        A[(4 * c4 + 1) * 72 + ch] = __float2half_rn(v.y);
        A[(4 * c4 + 2) * 72 + ch] = __float2half_rn(v.z);
        A[(4 * c4 + 3) * 72 + ch] = __float2half_rn(v.w);
    }
    __syncthreads();

    const uint32_t a_lane = a_u + (uint32_t)((lane & 15) * 72 + ((lane >> 4) << 3)) * 2u;
    const uint32_t* Bb = (const uint32_t*)(Bst + wid * 32 * 72);

    float acc[8][4][4];
#pragma unroll
    for (int mt = 0; mt < 8; mt++)
#pragma unroll
        for (int nt = 0; nt < 4; nt++)
#pragma unroll
            for (int r = 0; r < 4; r++) acc[mt][nt][r] = 0.f;

#pragma unroll
    for (int s = 0; s < 4; s++) {            // four k16 steps (K=64)
        uint32_t b0f[4], b1f[4];
#pragma unroll
        for (int nt = 0; nt < 4; nt++) {
            const int bw = (nt * 8 + g_) * 36 + s * 8 + tig;
            b0f[nt] = Bb[bw];
            b1f[nt] = Bb[bw + 4];
        }
        const uint32_t a_s = a_lane + (uint32_t)(s * 32);
#pragma unroll
        for (int mt = 0; mt < 8; mt++) {
            uint32_t a0, a1, a2, a3;
            ldsm4(a0, a1, a2, a3, a_s + (uint32_t)(mt * 16 * 72 * 2));
#pragma unroll
            for (int nt = 0; nt < 4; nt++)
                mma_f16(acc[mt][nt], a0, a1, a2, a3, b0f[nt], b1f[nt]);
        }
    }

    // epilogue: + bias, write fp16 P'
    __half2* out2 = (__half2*)(g_proj_h + (((size_t)n << 12) + cell0) * 256);
#pragma unroll
    for (int mt = 0; mt < 8; mt++) {
#pragma unroll
        for (int nt = 0; nt < 4; nt++) {
            const int c = wid * 32 + nt * 8 + 2 * tig;
            const float bv0 = bf[c], bv1 = bf[c + 1];
            const int r0 = mt * 16 + g_;
            out2[r0 * 128 + (c >> 1)] =
                __floats2half2_rn(acc[mt][nt][0] + bv0, acc[mt][nt][1] + bv1);
            out2[(r0 + 8) * 128 + (c >> 1)] =
                __floats2half2_rn(acc[mt][nt][2] + bv0, acc[mt][nt][3] + bv1);
        }
    }
}

// ---------- main kernel ----------
__global__ __launch_bounds__(NTHR, 1)
void liif_hmma_kernel(const float* __restrict__ w0, const float* __restrict__ w4,
                      const float* __restrict__ b1, const float* __restrict__ b2,
                      const float* __restrict__ b3, const float* __restrict__ b4,
                      float* __restrict__ out)
{
    extern __shared__ __half smem_h[];
    __half* Xs = smem_h;                         // 128 x 264 halves
    __half* Bs = smem_h + 128 * XS_H;            // 8 warps x 2 bufs x 2304 halves
    const uint32_t xs_u = smem_u32(Xs);
    const uint32_t bs_u = smem_u32(Bs);

    __shared__ float s_bias[3][256];
    __shared__ float s_w0r[2][256];
    __shared__ float s_w4[772];
    __shared__ float s_b4[3];
    __shared__ int   s_idx[4][QT];
    __shared__ float s_rel[4][2][QT];
    __shared__ float s_area[4][QT];
    __shared__ float s_wt[4][QT];
    __shared__ float s_red[128][2][3];

    const int tid  = threadIdx.x;
    const int wid  = tid >> 5;
    const int lane = tid & 31;
    const int g_   = lane >> 2, tig = lane & 3;
    const int n    = blockIdx.y;
    const int q0   = blockIdx.x * QT;

    // per-warp B strip copy: stage st (layer st>>2, tile st&3) -> buffer buf
    auto prefetch = [&](int buf, int st) {
        const int l2 = st >> 2, t2 = st & 3;
        const uint32_t dst0 = bs_u + (uint32_t)(wid * 2 * BW_BUF + buf * BW_BUF) * 2u;
#pragma unroll
        for (int j = 0; j < 8; j++) {
            const int e = lane + 32 * j;
            const int row = e >> 3, ch = e & 7;          // n-row 0..31, 16B chunk 0..7
            const __half* src = g_wh + (((l2 * 256 + wid * 32 + row) << 8) + t2 * 64 + ch * 8);
            cp16(dst0 + (uint32_t)(row * BW_H + ch * 8) * 2u, src);
        }
        cp_commit();
    };

    prefetch(0, 0);     // stage 0 in flight during setup

    for (int i = tid; i < 256; i += NTHR) {
        s_bias[0][i] = b1[i]; s_bias[1][i] = b2[i]; s_bias[2][i] = b3[i];
        s_w0r[0][i] = w0[64 * 256 + i]; s_w0r[1][i] = w0[65 * 256 + i];
    }
    for (int i = tid; i < 768; i += NTHR) s_w4[i] = w4[i];
    if (tid < 3) s_b4[tid] = b4[tid];

    // per-query geometry, one corner per thread (validated math from R1/R3)
    if (tid < 128) {
        const int t = tid >> 5, i = tid & 31;
        const int q = q0 + i;
        const int yq = q >> 8, xq = q & 255;
        const float c0 = (2.f * (float)yq + 1.f) * (1.f / 256.f) - 1.f;
        const float c1 = (2.f * (float)xq + 1.f) * (1.f / 256.f) - 1.f;
        const float lo = (float)(-1.0 + 1e-6), hi = (float)(1.0 - 1e-6);
        const double vx = (t < 2) ? -1.0 : 1.0;
        const double vy = (t & 1) ? 1.0 : -1.0;
        const float shx = (float)(vx * (1.0 / 64.0) + 1e-6);
        const float shy = (float)(vy * (1.0 / 64.0) + 1e-6);
        const float cc0 = fminf(fmaxf(c0 + shx, lo), hi);
        const float cc1 = fminf(fmaxf(c1 + shy, lo), hi);
        int iy = (int)rintf(((cc0 + 1.f) * 64.f - 1.f) * 0.5f);
        int ix = (int)rintf(((cc1 + 1.f) * 64.f - 1.f) * 0.5f);
        iy = min(max(iy, 0), 63); ix = min(max(ix, 0), 63);
        const float qc0 = (2.f * (float)iy + 1.f) * (1.f / 64.f) - 1.f;
        const float qc1 = (2.f * (float)ix + 1.f) * (1.f / 64.f) - 1.f;
        const float r0 = (c0 - qc0) * 64.f;
        const float r1 = (c1 - qc1) * 64.f;
        s_idx[t][i] = iy * 64 + ix;
        s_rel[t][0][i] = r0; s_rel[t][1][i] = r1;
        s_area[t][i] = fabsf(r0 * r1) + 1e-9f;
    }
    __syncthreads();

    // area weights (read only after later barriers)
    if (tid < QT) {
        const float a0 = s_area[0][tid], a1 = s_area[1][tid];
        const float a2 = s_area[2][tid], a3 = s_area[3][tid];
        const float tot = a0 + a1 + a2 + a3;
        s_wt[0][tid] = a3 / tot; s_wt[1][tid] = a2 / tot;
        s_wt[2][tid] = a1 / tot; s_wt[3][tid] = a0 / tot;
    }

    // h0 build: thread = (row, 128-col half); P' fp16 -> fp32 math -> fp16
    {
        const int row = tid >> 1, hseg = tid & 1;
        const int t = row >> 5, i = row & 31;
        const int idx = s_idx[t][i];
        const float r0 = s_rel[t][0][i], r1 = s_rel[t][1][i];
        const uint4* pp = (const uint4*)(g_proj_h + (((size_t)n << 12) + idx) * 256
                                         + hseg * 128);
        __half2* xw = (__half2*)Xs + row * 132 + hseg * 64;
#pragma unroll
        for (int j = 0; j < 16; j++) {
            const uint4 q = pp[j];
            uint32_t w[4] = {q.x, q.y, q.z, q.w};
            const int cb = hseg * 128 + j * 8;
#pragma unroll
            for (int u = 0; u < 4; u++) {
                const float2 p = __half22float2(*(const __half2*)&w[u]);
                const int c = cb + 2 * u;
                const float v0 = fmaf(r0, s_w0r[0][c],     fmaf(r1, s_w0r[1][c],     p.x));
                const float v1 = fmaf(r0, s_w0r[0][c + 1], fmaf(r1, s_w0r[1][c + 1], p.y));
                xw[j * 4 + u] = __floats2half2_rn(fmaxf(v0, 0.f), fmaxf(v1, 0.f));
            }
        }
    }
    __syncthreads();

    // ldmatrix per-lane A base: row = lane&15, k-halves add = (lane>>4)*8
    const int lrow = lane & 15;
    const int kadd = (lane >> 4) << 3;
    const uint32_t a_lane = xs_u + (uint32_t)(lrow * XS_H + kadd) * 2u;

    const uint32_t* Bw = (const uint32_t*)(Bs + wid * 2 * BW_BUF);

    float acc[8][4][4];
#pragma unroll
    for (int mt = 0; mt < 8; mt++)
#pragma unroll
        for (int nt = 0; nt < 4; nt++)
#pragma unroll
            for (int r = 0; r < 4; r++) acc[mt][nt][r] = 0.f;

    int buf = 0;
#pragma unroll 1
    for (int st = 0; st < NSTAGES; st++) {
        const int tile = st & 3;

        if (st + 1 < NSTAGES) { prefetch(buf ^ 1, st + 1); cp_wait<1>(); }
        else                  { cp_wait<0>(); }
        // no __syncthreads: B strips are warp-private, Xs is read-only here

        const uint32_t* Bb = Bw + buf * (BW_BUF / 2);
        const uint32_t a_st = a_lane + (uint32_t)(tile * 64) * 2u;   // halves -> bytes

#pragma unroll
        for (int s = 0; s < 4; s++) {            // four k16 steps per 64-k tile
            uint32_t b0f[4], b1f[4];
#pragma unroll
            for (int nt = 0; nt < 4; nt++) {
                const int bw = (nt * 8 + g_) * 36 + s * 8 + tig;
                b0f[nt] = Bb[bw];
                b1f[nt] = Bb[bw + 4];
            }
            const uint32_t a_s = a_st + (uint32_t)(s * 32);
#pragma unroll
            for (int mt = 0; mt < 8; mt++) {
                uint32_t a0, a1, a2, a3;
                ldsm4(a0, a1, a2, a3, a_s + (uint32_t)(mt * 16 * XS_H * 2));
#pragma unroll
                for (int nt = 0; nt < 4; nt++)
                    mma_f16(acc[mt][nt], a0, a1, a2, a3, b0f[nt], b1f[nt]);
            }
        }
        buf ^= 1;

        if (tile == 3) {                         // layer boundary
            const int le = st >> 2;
            __syncthreads();                     // all reads of Xs done
#pragma unroll
            for (int mt = 0; mt < 8; mt++) {
#pragma unroll
                for (int nt = 0; nt < 4; nt++) {
                    const int c = wid * 32 + nt * 8 + 2 * tig;
                    const float bv0 = s_bias[le][c], bv1 = s_bias[le][c + 1];
                    const float v00 = fmaxf(acc[mt][nt][0] + bv0, 0.f);
                    const float v01 = fmaxf(acc[mt][nt][1] + bv1, 0.f);
                    const float v10 = fmaxf(acc[mt][nt][2] + bv0, 0.f);
                    const float v11 = fmaxf(acc[mt][nt][3] + bv1, 0.f);
                    const int r0 = mt * 16 + g_;
                    __half2* xw = (__half2*)Xs;
                    xw[r0 * 132 + wid * 16 + nt * 4 + tig]       = __floats2half2_rn(v00, v01);
                    xw[(r0 + 8) * 132 + wid * 16 + nt * 4 + tig] = __floats2half2_rn(v10, v11);
                    acc[mt][nt][0] = 0.f; acc[mt][nt][1] = 0.f;
                    acc[mt][nt][2] = 0.f; acc[mt][nt][3] = 0.f;
                }
            }
            __syncthreads();                     // writes visible before next layer
        }
    }

    // final 256->3 layer, fp32: thread = (row, k-half)
    {
        const int row = tid >> 1, hseg = tid & 1;
        const __half2* xw = (const __half2*)Xs + row * 132 + hseg * 64;
        float a0 = 0.f, a1 = 0.f, a2 = 0.f;
#pragma unroll 16
        for (int j = 0; j < 64; j++) {
            const float2 y = __half22float2(xw[j]);
            const float* wr = &s_w4[(hseg * 128 + 2 * j) * 3];
            a0 = fmaf(y.x, wr[0], fmaf(y.y, wr[3], a0));
            a1 = fmaf(y.x, wr[1], fmaf(y.y, wr[4], a1));
            a2 = fmaf(y.x, wr[2], fmaf(y.y, wr[5], a2));
        }
        s_red[row][hseg][0] = a0; s_red[row][hseg][1] = a1; s_red[row][hseg][2] = a2;
    }
    __syncthreads();

    // area-weighted combine + NCHW write
    if (tid < 96) {
        const int i = tid / 3;
        const int o = tid - 3 * (tid / 3);
        float v = 0.f;
#pragma unroll
        for (int t = 0; t < 4; t++) {
            const int row = t * 32 + i;
            const float p = s_b4[o] + s_red[row][0][o] + s_red[row][1][o];
            v += s_wt[t][i] * p;
        }
        out[((size_t)n * 3 + o) * 65536 + q0 + i] = v;
    }
}

} // anonymous namespace

extern "C" void kernel_launch(void* const* d_in, const int* in_sizes, int n_in,
                              void* d_out, int out_size)
{
    (void)in_sizes; (void)n_in; (void)out_size;
    const float* feat = (const float*)d_in[0];
    const float* w0 = (const float*)d_in[1];
    const float* b0 = (const float*)d_in[2];
    const float* w1 = (const float*)d_in[3];
    const float* b1 = (const float*)d_in[4];
    const float* w2 = (const float*)d_in[5];
    const float* b2 = (const float*)d_in[6];
    const float* w3 = (const float*)d_in[7];
    const float* b3 = (const float*)d_in[8];
    const float* w4 = (const float*)d_in[9];
    const float* b4 = (const float*)d_in[10];

    prep_w_kernel<<<(196608 + 16384 + 255) / 256, 256>>>(w1, w2, w3, w0);

    const size_t proj_shmem = (128 * 72 + 8 * 32 * 72) * sizeof(__half)
                            + 256 * sizeof(float);               // 56320 B
    cudaFuncSetAttribute(prep_proj_kernel,
                         cudaFuncAttributeMaxDynamicSharedMemorySize, (int)proj_shmem);
    prep_proj_kernel<<<128, 256, proj_shmem>>>(feat, w0, b0);

    const size_t shmem = (size_t)(128 * XS_H + 8 * 2 * BW_BUF) * sizeof(__half); // 141312 B
    cudaFuncSetAttribute(liif_hmma_kernel,
                         cudaFuncAttributeMaxDynamicSharedMemorySize, (int)shmem);
    dim3 grid(65536 / QT, 4);
    liif_hmma_kernel<<<grid, NTHR, shmem>>>(w0, w4, b1, b2, b3, b4, (float*)d_out);
}